// round 3
// baseline (speedup 1.0000x reference)
#include <cuda_runtime.h>

#define BATCH       16384
#define NUM_FIELDS  20
#define NUM_FEAT    100000
#define LATENT      64

// One warp per batch row; lane l owns latent dims [2l, 2l+1].
// All 20 field gathers are loaded into a register array FIRST (forcing
// MLP=20 per warp), then accumulated. 64-reg budget (4 blocks/SM, 32 warps)
// trades occupancy for per-warp memory-level parallelism: 32x20 in-flight
// 256B gathers per SM vs ~51x8 when regs were capped at 32.
__global__ void __launch_bounds__(256, 4)
ffm_kernel(const int* __restrict__ x,
           const float* __restrict__ emb,
           float* __restrict__ out)
{
    const int warp = (blockIdx.x * blockDim.x + threadIdx.x) >> 5;
    const int lane = threadIdx.x & 31;
    if (warp >= BATCH) return;

    // Lanes 0..19 hold this row's feature indices (also the linear term).
    int xv = 0;
    if (lane < NUM_FIELDS) xv = __ldg(&x[warp * NUM_FIELDS + lane]);

    // Phase 1: issue all 20 independent gathers back-to-back.
    float2 v[NUM_FIELDS];
    #pragma unroll
    for (int f = 0; f < NUM_FIELDS; f++) {
        const int idx = __shfl_sync(0xffffffffu, xv, f);
        v[f] = __ldg(reinterpret_cast<const float2*>(
            emb + ((size_t)f * NUM_FEAT + (size_t)idx) * LATENT) + lane);
    }

    // Phase 2: accumulate.
    float2 s   = make_float2(0.f, 0.f);
    float  ssq = 0.f;
    #pragma unroll
    for (int f = 0; f < NUM_FIELDS; f++) {
        s.x += v[f].x;
        s.y += v[f].y;
        ssq  = fmaf(v[f].x, v[f].x, fmaf(v[f].y, v[f].y, ssq));
    }

    // Per-lane partial: s_x^2 + s_y^2 - sum v^2 over this lane's 2 dims.
    float t   = fmaf(s.x, s.x, s.y * s.y) - ssq;
    float lin = (float)xv;   // lanes >= NUM_FIELDS contribute 0

    #pragma unroll
    for (int off = 16; off > 0; off >>= 1) {
        t   += __shfl_down_sync(0xffffffffu, t,   off);
        lin += __shfl_down_sync(0xffffffffu, lin, off);
    }

    if (lane == 0) out[warp] = lin + 0.5f * t;
}

extern "C" void kernel_launch(void* const* d_in, const int* in_sizes, int n_in,
                              void* d_out, int out_size)
{
    const int*   x   = (const int*)d_in[0];
    // d_in[1] = field_indices (0..19), implicit in layout.
    const float* emb = (const float*)d_in[2];
    float*       out = (float*)d_out;

    const int warps_per_block = 256 / 32;                               // 8
    const int blocks = (BATCH + warps_per_block - 1) / warps_per_block;  // 2048
    ffm_kernel<<<blocks, 256>>>(x, emb, out);
}

// round 4
// speedup vs baseline: 1.2060x; 1.2060x over previous
#include <cuda_runtime.h>

#define BATCH       16384
#define NUM_FIELDS  20
#define NUM_FEAT    100000
#define LATENT      64

// One warp per batch row; lane l owns latent dims [2l, 2l+1].
// Identical memory pattern to the R1 best (20 independent coalesced 256B
// float2 gathers per warp, incremental accumulation, regs<=32), but with
// 128-thread CTAs (grid 4096): same warps/SM, 4x finer scheduling quantum
// to tighten the second-wave tail. The kernel is pinned at the ~6300 B/cyc
// LTS cap (83.9 MB -> ~12.2us floor); this targets the last scheduling slack.
__global__ void __launch_bounds__(128, 16)
ffm_kernel(const int* __restrict__ x,
           const float* __restrict__ emb,
           float* __restrict__ out)
{
    const int warp = (blockIdx.x * blockDim.x + threadIdx.x) >> 5;
    const int lane = threadIdx.x & 31;
    if (warp >= BATCH) return;

    // Lanes 0..19 hold this row's feature indices (also the linear term).
    int xv = 0;
    if (lane < NUM_FIELDS) xv = __ldg(&x[warp * NUM_FIELDS + lane]);

    float2 s   = make_float2(0.f, 0.f);
    float  ssq = 0.f;

    #pragma unroll
    for (int f = 0; f < NUM_FIELDS; f++) {
        const int idx = __shfl_sync(0xffffffffu, xv, f);
        const float2 v = __ldg(reinterpret_cast<const float2*>(
            emb + ((size_t)f * NUM_FEAT + (size_t)idx) * LATENT) + lane);
        s.x += v.x;
        s.y += v.y;
        ssq  = fmaf(v.x, v.x, fmaf(v.y, v.y, ssq));
    }

    // Per-lane partial: s_x^2 + s_y^2 - sum v^2 over this lane's 2 dims.
    float t   = fmaf(s.x, s.x, s.y * s.y) - ssq;
    float lin = (float)xv;   // lanes >= NUM_FIELDS contribute 0

    #pragma unroll
    for (int off = 16; off > 0; off >>= 1) {
        t   += __shfl_down_sync(0xffffffffu, t,   off);
        lin += __shfl_down_sync(0xffffffffu, lin, off);
    }

    if (lane == 0) out[warp] = lin + 0.5f * t;
}

extern "C" void kernel_launch(void* const* d_in, const int* in_sizes, int n_in,
                              void* d_out, int out_size)
{
    const int*   x   = (const int*)d_in[0];
    // d_in[1] = field_indices (0..19), implicit in layout.
    const float* emb = (const float*)d_in[2];
    float*       out = (float*)d_out;

    const int warps_per_block = 128 / 32;                               // 4
    const int blocks = (BATCH + warps_per_block - 1) / warps_per_block;  // 4096
    ffm_kernel<<<blocks, 128>>>(x, emb, out);
}